// round 15
// baseline (speedup 1.0000x reference)
#include <cuda_runtime.h>
#include <cstdint>
#include <cstddef>

// ---------------- problem constants ----------------
#define T_STEPS 16384
#define HDIM    512
#define GDIM    1536          // 3*H
#define NCTA    32
#define HPC     16            // h elements per CTA
#define RPC     48            // W_hh rows per CTA (3 gates x HPC)
#define NTH     384           // 12 warps; 8 lanes per row
#define POLLW   11            // poller / h-stager / gi-prefetch warp
#define PD      8             // gi ring depth

// ---------------- device scratch ----------------
__device__ float              g_gi[(size_t)T_STEPS * GDIM]; // gi + folded biases
__device__ unsigned long long g_ht[2][HDIM];                // {tag:hi32, h:lo32}

// ---------------- GEMM: gi = x @ W_ih^T + bih (+bhh for r,z gates) ----------
#define BM 128
#define BN 128
#define BK 8

__global__ void __launch_bounds__(256) gemm_gi(
    const float* __restrict__ x, const float* __restrict__ Wih,
    const float* __restrict__ bih, const float* __restrict__ bhh) {
    // block (0,0) resets tagged h buffers: tag=0,val=0 (buf0 = valid h(0))
    if (blockIdx.x == 0 && blockIdx.y == 0) {
        unsigned long long* p = &g_ht[0][0];
        for (int i = threadIdx.x; i < 2 * HDIM; i += 256) p[i] = 0ULL;
    }

    __shared__ __align__(16) float As[BK][BM];
    __shared__ __align__(16) float Bs[BK][BN];
    const int bn  = blockIdx.x;
    const int bm  = blockIdx.y;
    const int tid = threadIdx.x;
    const int tx  = tid & 15;
    const int ty  = tid >> 4;

    const int lrow = tid >> 1;
    const int lseg = (tid & 1) * 4;
    const float* xp = x   + (size_t)(bm * BM + lrow) * HDIM + lseg;
    const float* wp = Wih + (size_t)(bn * BN + lrow) * HDIM + lseg;

    float acc[8][8];
#pragma unroll
    for (int i = 0; i < 8; i++)
#pragma unroll
        for (int j = 0; j < 8; j++) acc[i][j] = 0.f;

    for (int k0 = 0; k0 < HDIM; k0 += BK) {
        float4 av = *(const float4*)(xp + k0);
        float4 bv = *(const float4*)(wp + k0);
        As[lseg + 0][lrow] = av.x; As[lseg + 1][lrow] = av.y;
        As[lseg + 2][lrow] = av.z; As[lseg + 3][lrow] = av.w;
        Bs[lseg + 0][lrow] = bv.x; Bs[lseg + 1][lrow] = bv.y;
        Bs[lseg + 2][lrow] = bv.z; Bs[lseg + 3][lrow] = bv.w;
        __syncthreads();
#pragma unroll
        for (int k = 0; k < BK; k++) {
            float4 a0 = *(const float4*)&As[k][ty * 8];
            float4 a1 = *(const float4*)&As[k][ty * 8 + 4];
            float4 b0 = *(const float4*)&Bs[k][tx * 8];
            float4 b1 = *(const float4*)&Bs[k][tx * 8 + 4];
            float a[8] = {a0.x, a0.y, a0.z, a0.w, a1.x, a1.y, a1.z, a1.w};
            float b[8] = {b0.x, b0.y, b0.z, b0.w, b1.x, b1.y, b1.z, b1.w};
#pragma unroll
            for (int i = 0; i < 8; i++)
#pragma unroll
                for (int j = 0; j < 8; j++)
                    acc[i][j] = fmaf(a[i], b[j], acc[i][j]);
        }
        __syncthreads();
    }
#pragma unroll
    for (int i = 0; i < 8; i++) {
        int row = bm * BM + ty * 8 + i;
        float* gp = &g_gi[(size_t)row * GDIM + bn * BN + tx * 8];
#pragma unroll
        for (int j = 0; j < 8; j++) {
            int col = bn * BN + tx * 8 + j;
            float b = bih[col];
            if (col < 2 * HDIM) b += bhh[col];   // fold bhh for r,z gates only
            gp[j] = acc[i][j] + b;
        }
    }
}

// ---------------- scan helpers ----------------
__device__ __forceinline__ uint32_t smem_u32(const void* p) {
    uint32_t a;
    asm("{ .reg .u64 t; cvta.to.shared.u64 t, %1; cvt.u32.u64 %0, t; }"
        : "=r"(a) : "l"(p));
    return a;
}
__device__ __forceinline__ float f32x2_hsum(unsigned long long a) {
    float lo, hi;
    asm("mov.b64 {%0,%1}, %2;" : "=f"(lo), "=f"(hi) : "l"(a));
    return lo + hi;
}
__device__ __forceinline__ float mufu_tanh(float x) {
    float r;
    asm("tanh.approx.f32 %0, %1;" : "=f"(r) : "f"(x));
    return r;
}
__device__ __forceinline__ float mufu_sigmoid(float x) {
    return fmaf(mufu_tanh(0.5f * x), 0.5f, 0.5f);
}

// ---------------- persistent GRU scan ----------------
__global__ void __launch_bounds__(NTH, 1) gru_scan(
    const float* __restrict__ Whh, const float* __restrict__ bhh,
    float* __restrict__ out) {
    __shared__ __align__(16) float h_s[2][HDIM];    // staged h, double-buffered
    __shared__ __align__(16) float ring[PD][RPC];   // gi prefetch ring
    __shared__ unsigned sflag[2][16];               // per-stripe ready flags
    __shared__ float red_s[RPC];
    __shared__ float bhhn_s[HPC];                   // bhh for n gate only

    const int c   = blockIdx.x;
    const int tid = threadIdx.x;
    const int wid = tid >> 5;
    const int l   = tid & 31;
    const int lr  = tid >> 3;            // local row 0..47
    const int j   = tid & 7;             // lane within row

    // global row (gate-major: r,z,n blocks of HPC)
    const int gr = (lr / HPC) * HDIM + c * HPC + (lr % HPC);

    // ---- weights resident in registers: 16 x (u64,u64) ----
    unsigned long long wlo[16], whi[16];
    {
        const ulonglong2* wp =
            (const ulonglong2*)(Whh + (size_t)gr * HDIM + j * 4);
#pragma unroll
        for (int s = 0; s < 16; ++s) {
            ulonglong2 wv = __ldg(wp + s * 8);   // stride 128B
            wlo[s] = wv.x; whi[s] = wv.y;
        }
    }

    if (tid < HPC) bhhn_s[tid] = bhh[2 * HDIM + c * HPC + tid];
    if (tid < 32) sflag[tid >> 4][tid & 15] = 0u;

    // ---- gi ring prologue: slots 0..6 (poller warp, lanes 0-11) ----
    const uint32_t ring_u32  = smem_u32(&ring[0][0]);
    const uint32_t sflag_u32 = smem_u32(&sflag[0][0]);
    if (wid == POLLW) {
#pragma unroll
        for (int p = 0; p < PD - 1; p++) {
            if (l < 12) {
                const float* src = &g_gi[(size_t)p * GDIM +
                                         (l >> 2) * HDIM + c * HPC + (l & 3) * 4];
                uint32_t dst = ring_u32 + (uint32_t)((p * RPC + l * 4) * 4);
                asm volatile("cp.async.cg.shared.global [%0], [%1], 16;"
                             :: "r"(dst), "l"(src));
            }
            asm volatile("cp.async.commit_group;");
        }
        asm volatile("cp.async.wait_group 0;");
    }

    const int hbase = c * HPC;
    float hprev = 0.f;
    __syncthreads();

    for (int t = 0; t < T_STEPS; ++t) {
        const int par = t & 1;
        const unsigned tgt = (unsigned)(t + 1);

        // ---- poller warp: per-stripe capture -> stage -> flag release ----
        if (wid == POLLW) {
            const unsigned long long* hb = &g_ht[par][0];
            const unsigned long long thr = (unsigned long long)(unsigned)t << 32;
            unsigned long long q[16];
#pragma unroll
            for (int i = 0; i < 16; i++)
                asm volatile("ld.relaxed.gpu.global.u64 %0, [%1];"
                             : "=l"(q[i]) : "l"(hb + l + 32 * i));
            unsigned pend = 0xFFFFu;
            do {
#pragma unroll
                for (int i = 0; i < 16; i++) {
                    if (pend & (1u << i)) {
                        if (__all_sync(0xffffffffu, q[i] >= thr)) {
                            h_s[par][l + 32 * i] =
                                __uint_as_float((unsigned)q[i]);
                            __syncwarp();
                            if (l == 0)
                                asm volatile(
                                    "st.release.cta.shared.u32 [%0], %1;"
                                    :: "r"(sflag_u32 + (par * 16 + i) * 4),
                                       "r"(tgt) : "memory");
                            pend &= ~(1u << i);
                        } else {
                            asm volatile("ld.relaxed.gpu.global.u64 %0, [%1];"
                                         : "=l"(q[i]) : "l"(hb + l + 32 * i));
                        }
                    }
                }
            } while (pend);
            // gi(t+7) into ring slot (t+7)&7 (safe: capture passed => consumed)
            {
                int tp = t + PD - 1;
                if (tp >= T_STEPS) tp = T_STEPS - 1;
                if (l < 12) {
                    const float* src = &g_gi[(size_t)tp * GDIM +
                                             (l >> 2) * HDIM + c * HPC + (l & 3) * 4];
                    uint32_t dst = ring_u32 +
                        (uint32_t)(((tp & (PD - 1)) * RPC + l * 4) * 4);
                    asm volatile("cp.async.cg.shared.global [%0], [%1], 16;"
                                 :: "r"(dst), "l"(src));
                }
                asm volatile("cp.async.commit_group;");
                asm volatile("cp.async.wait_group 6;");
            }
        }

        // ---- incremental matvec: FMA stripes as they become ready ----
        const float* hv = &h_s[par][0] + j * 4;
        unsigned long long a0 = 0ull, a1 = 0ull, a2 = 0ull, a3 = 0ull;
        unsigned done = 0u;
        do {
            unsigned f = 0u;
            if (l < 16)
                asm volatile("ld.acquire.cta.shared.u32 %0, [%1];"
                             : "=r"(f)
                             : "r"(sflag_u32 + (par * 16 + l) * 4) : "memory");
            unsigned ready = __ballot_sync(0xffffffffu, (l < 16) && (f >= tgt));
            unsigned todo = ready & ~done & 0xFFFFu;
#pragma unroll
            for (int s = 0; s < 16; s++) {
                if (todo & (1u << s)) {
                    ulonglong2 p0 = *(const ulonglong2*)(hv + s * 32);
                    if (s & 1) {
                        asm("fma.rn.f32x2 %0, %1, %2, %0;" : "+l"(a2) : "l"(wlo[s]), "l"(p0.x));
                        asm("fma.rn.f32x2 %0, %1, %2, %0;" : "+l"(a3) : "l"(whi[s]), "l"(p0.y));
                    } else {
                        asm("fma.rn.f32x2 %0, %1, %2, %0;" : "+l"(a0) : "l"(wlo[s]), "l"(p0.x));
                        asm("fma.rn.f32x2 %0, %1, %2, %0;" : "+l"(a1) : "l"(whi[s]), "l"(p0.y));
                    }
                }
            }
            done |= todo;
        } while (done != 0xFFFFu);

        float acc = (f32x2_hsum(a0) + f32x2_hsum(a1)) +
                    (f32x2_hsum(a2) + f32x2_hsum(a3));
        acc += __shfl_xor_sync(0xffffffffu, acc, 4);
        acc += __shfl_xor_sync(0xffffffffu, acc, 2);
        acc += __shfl_xor_sync(0xffffffffu, acc, 1);
        if (j == 0) red_s[lr] = acc;
        __syncthreads();                 // the ONE barrier per step

        // ---- gate math + tagged publish (warp 0, lanes 0..15) ----
        if (wid == 0) {
            float hnew = 0.f;
            if (l < HPC) {
                const float* gi = &ring[t & (PD - 1)][0];
                float r = mufu_sigmoid(gi[l]       + red_s[l]);
                float z = mufu_sigmoid(gi[HPC + l] + red_s[HPC + l]);
                float n = mufu_tanh(fmaf(r, red_s[2 * HPC + l] + bhhn_s[l],
                                         gi[2 * HPC + l]));
                hnew = n + z * (hprev - n);          // (1-z)*n + z*h
                hprev = hnew;
                unsigned long long pk =
                    (unsigned long long)__float_as_uint(hnew) |
                    ((unsigned long long)tgt << 32);
                asm volatile("st.relaxed.gpu.global.u64 [%0], %1;"
                             :: "l"(&g_ht[par ^ 1][hbase + l]), "l"(pk) : "memory");
                out[(size_t)t * HDIM + hbase + l] = hnew;  // off the serial path
            }
        }
    }
}

// ---------------- launch ----------------
extern "C" void kernel_launch(void* const* d_in, const int* in_sizes, int n_in,
                              void* d_out, int out_size) {
    const float* x   = (const float*)d_in[0];
    const float* Wih = (const float*)d_in[1];
    const float* Whh = (const float*)d_in[2];
    const float* bih = (const float*)d_in[3];
    const float* bhh = (const float*)d_in[4];
    float* out = (float*)d_out;

    dim3 ggrid(GDIM / BN, T_STEPS / BM);   // (12, 128)
    gemm_gi<<<ggrid, 256>>>(x, Wih, bih, bhh);
    gru_scan<<<NCTA, NTH>>>(Whh, bhh, out);
}

// round 16
// speedup vs baseline: 1.4884x; 1.4884x over previous
#include <cuda_runtime.h>
#include <cstdint>
#include <cstddef>

// ---------------- problem constants ----------------
#define T_STEPS 16384
#define HDIM    512
#define GDIM    1536          // 3*H
#define NCTA    32
#define HPC     16            // h elements per CTA
#define RPC     48            // W_hh rows per CTA (3 gates x HPC)
#define NTH     384           // 12 warps; 8 lanes per row
#define POLLW   11            // poller / h-stager warp
#define PREFW   10            // gi-prefetch warp
#define PD      8             // gi ring depth

// ---------------- device scratch ----------------
__device__ float              g_gi[(size_t)T_STEPS * GDIM]; // gi + folded biases
__device__ unsigned long long g_ht[2][HDIM];                // {tag:hi32, h:lo32}

// ---------------- GEMM: gi = x @ W_ih^T + bih (+bhh for r,z gates) ----------
#define BM 128
#define BN 128
#define BK 8

__global__ void __launch_bounds__(256) gemm_gi(
    const float* __restrict__ x, const float* __restrict__ Wih,
    const float* __restrict__ bih, const float* __restrict__ bhh) {
    // block (0,0) resets tagged h buffers: tag=0,val=0 (buf0 = valid h(0))
    if (blockIdx.x == 0 && blockIdx.y == 0) {
        unsigned long long* p = &g_ht[0][0];
        for (int i = threadIdx.x; i < 2 * HDIM; i += 256) p[i] = 0ULL;
    }

    __shared__ __align__(16) float As[BK][BM];
    __shared__ __align__(16) float Bs[BK][BN];
    const int bn  = blockIdx.x;
    const int bm  = blockIdx.y;
    const int tid = threadIdx.x;
    const int tx  = tid & 15;
    const int ty  = tid >> 4;

    const int lrow = tid >> 1;
    const int lseg = (tid & 1) * 4;
    const float* xp = x   + (size_t)(bm * BM + lrow) * HDIM + lseg;
    const float* wp = Wih + (size_t)(bn * BN + lrow) * HDIM + lseg;

    float acc[8][8];
#pragma unroll
    for (int i = 0; i < 8; i++)
#pragma unroll
        for (int j = 0; j < 8; j++) acc[i][j] = 0.f;

    for (int k0 = 0; k0 < HDIM; k0 += BK) {
        float4 av = *(const float4*)(xp + k0);
        float4 bv = *(const float4*)(wp + k0);
        As[lseg + 0][lrow] = av.x; As[lseg + 1][lrow] = av.y;
        As[lseg + 2][lrow] = av.z; As[lseg + 3][lrow] = av.w;
        Bs[lseg + 0][lrow] = bv.x; Bs[lseg + 1][lrow] = bv.y;
        Bs[lseg + 2][lrow] = bv.z; Bs[lseg + 3][lrow] = bv.w;
        __syncthreads();
#pragma unroll
        for (int k = 0; k < BK; k++) {
            float4 a0 = *(const float4*)&As[k][ty * 8];
            float4 a1 = *(const float4*)&As[k][ty * 8 + 4];
            float4 b0 = *(const float4*)&Bs[k][tx * 8];
            float4 b1 = *(const float4*)&Bs[k][tx * 8 + 4];
            float a[8] = {a0.x, a0.y, a0.z, a0.w, a1.x, a1.y, a1.z, a1.w};
            float b[8] = {b0.x, b0.y, b0.z, b0.w, b1.x, b1.y, b1.z, b1.w};
#pragma unroll
            for (int i = 0; i < 8; i++)
#pragma unroll
                for (int j = 0; j < 8; j++)
                    acc[i][j] = fmaf(a[i], b[j], acc[i][j]);
        }
        __syncthreads();
    }
#pragma unroll
    for (int i = 0; i < 8; i++) {
        int row = bm * BM + ty * 8 + i;
        float* gp = &g_gi[(size_t)row * GDIM + bn * BN + tx * 8];
#pragma unroll
        for (int j = 0; j < 8; j++) {
            int col = bn * BN + tx * 8 + j;
            float b = bih[col];
            if (col < 2 * HDIM) b += bhh[col];   // fold bhh for r,z gates only
            gp[j] = acc[i][j] + b;
        }
    }
}

// ---------------- scan helpers ----------------
__device__ __forceinline__ uint32_t smem_u32(const void* p) {
    uint32_t a;
    asm("{ .reg .u64 t; cvta.to.shared.u64 t, %1; cvt.u32.u64 %0, t; }"
        : "=r"(a) : "l"(p));
    return a;
}
__device__ __forceinline__ float f32x2_hsum(unsigned long long a) {
    float lo, hi;
    asm("mov.b64 {%0,%1}, %2;" : "=f"(lo), "=f"(hi) : "l"(a));
    return lo + hi;
}
__device__ __forceinline__ float mufu_tanh(float x) {
    float r;
    asm("tanh.approx.f32 %0, %1;" : "=f"(r) : "f"(x));
    return r;
}
__device__ __forceinline__ float mufu_sigmoid(float x) {
    return fmaf(mufu_tanh(0.5f * x), 0.5f, 0.5f);
}

// ---------------- persistent GRU scan ----------------
__global__ void __launch_bounds__(NTH, 1) gru_scan(
    const float* __restrict__ Whh, const float* __restrict__ bhh,
    float* __restrict__ out) {
    __shared__ __align__(16) float h_s[HDIM];       // staged hidden state
    __shared__ __align__(16) float ring[PD][RPC];   // gi prefetch ring
    __shared__ float red_s[RPC];
    __shared__ float bhhn_s[HPC];                   // bhh for n gate only

    const int c   = blockIdx.x;
    const int tid = threadIdx.x;
    const int wid = tid >> 5;
    const int l   = tid & 31;
    const int lr  = tid >> 3;            // local row 0..47
    const int j   = tid & 7;             // lane within row

    // global row (gate-major: r,z,n blocks of HPC)
    const int gr = (lr / HPC) * HDIM + c * HPC + (lr % HPC);

    // ---- weights resident in registers: 16 x (u64,u64) ----
    unsigned long long wlo[16], whi[16];
    {
        const ulonglong2* wp =
            (const ulonglong2*)(Whh + (size_t)gr * HDIM + j * 4);
#pragma unroll
        for (int s = 0; s < 16; ++s) {
            ulonglong2 wv = __ldg(wp + s * 8);   // stride 128B
            wlo[s] = wv.x; whi[s] = wv.y;
        }
    }

    if (tid < HPC) bhhn_s[tid] = bhh[2 * HDIM + c * HPC + tid];

    // ---- gi ring prologue: slots 0..6 (prefetch warp, lanes 0-11) ----
    const uint32_t ring_u32 = smem_u32(&ring[0][0]);
    if (wid == PREFW) {
#pragma unroll
        for (int p = 0; p < PD - 1; p++) {
            if (l < 12) {
                const float* src = &g_gi[(size_t)p * GDIM +
                                         (l >> 2) * HDIM + c * HPC + (l & 3) * 4];
                uint32_t dst = ring_u32 + (uint32_t)((p * RPC + l * 4) * 4);
                asm volatile("cp.async.cg.shared.global [%0], [%1], 16;"
                             :: "r"(dst), "l"(src));
            }
            asm volatile("cp.async.commit_group;");
        }
        asm volatile("cp.async.wait_group 0;");
    }

    const int hbase = c * HPC;
    float hprev = 0.f;
    __syncthreads();

    for (int t = 0; t < T_STEPS; ++t) {
        const int par = t & 1;

        // ---- poller warp: fused capture + straggler-only retry -> stage ----
        // (poller did bar.arrive at barB(t-1), so it is already polling while
        //  producers are still computing gates(t-1) -> loads in flight early)
        if (wid == POLLW) {
            const unsigned long long* hb = &g_ht[par][0];
            const unsigned long long thr = (unsigned long long)(unsigned)t << 32;
            unsigned long long q[16];
#pragma unroll
            for (int i = 0; i < 16; i++)
                asm volatile("ld.relaxed.gpu.global.u64 %0, [%1];"
                             : "=l"(q[i]) : "l"(hb + l + 32 * i));
            for (;;) {
                bool ok = true;
#pragma unroll
                for (int i = 0; i < 16; i++) ok &= (q[i] >= thr);
                if (__all_sync(0xffffffffu, ok)) break;
#pragma unroll
                for (int i = 0; i < 16; i++)
                    if (q[i] < thr)      // reload stale words only
                        asm volatile("ld.relaxed.gpu.global.u64 %0, [%1];"
                                     : "=l"(q[i]) : "l"(hb + l + 32 * i));
            }
            // stage h(t): strip tags (safe: own tag t implies local reads of
            // h_s(t-1) completed, since own warp0 passed barB(t-1))
#pragma unroll
            for (int i = 0; i < 16; i++)
                h_s[l + 32 * i] = __uint_as_float((unsigned)q[i]);
        }
        __syncthreads();                 // bar A: h_s + ring slot t ready

        // ---- gi(t+7) prefetch (warp 10, off the poller's critical path) ----
        // slot (t+7)&7 == (t-1)&7 was consumed at gates(t-1), which precedes
        // barA(t) release (warp0 arrives only after gates(t-1)).
        if (wid == PREFW) {
            int tp = t + PD - 1;
            if (tp >= T_STEPS) tp = T_STEPS - 1;
            if (l < 12) {
                const float* src = &g_gi[(size_t)tp * GDIM +
                                         (l >> 2) * HDIM + c * HPC + (l & 3) * 4];
                uint32_t dst = ring_u32 +
                    (uint32_t)(((tp & (PD - 1)) * RPC + l * 4) * 4);
                asm volatile("cp.async.cg.shared.global [%0], [%1], 16;"
                             :: "r"(dst), "l"(src));
            }
            asm volatile("cp.async.commit_group;");
            asm volatile("cp.async.wait_group 6;");
        }

        // ---- matvec: weights from regs, h from SMEM (broadcast LDS.128) ----
        const float* hv = h_s + j * 4;
        unsigned long long a0 = 0ull, a1 = 0ull, a2 = 0ull, a3 = 0ull;
#pragma unroll
        for (int s = 0; s < 16; s += 2) {
            ulonglong2 p0 = *(const ulonglong2*)(hv + s * 32);
            ulonglong2 p1 = *(const ulonglong2*)(hv + (s + 1) * 32);
            asm("fma.rn.f32x2 %0, %1, %2, %0;" : "+l"(a0) : "l"(wlo[s]),     "l"(p0.x));
            asm("fma.rn.f32x2 %0, %1, %2, %0;" : "+l"(a1) : "l"(whi[s]),     "l"(p0.y));
            asm("fma.rn.f32x2 %0, %1, %2, %0;" : "+l"(a2) : "l"(wlo[s + 1]), "l"(p1.x));
            asm("fma.rn.f32x2 %0, %1, %2, %0;" : "+l"(a3) : "l"(whi[s + 1]), "l"(p1.y));
        }
        float acc = (f32x2_hsum(a0) + f32x2_hsum(a1)) +
                    (f32x2_hsum(a2) + f32x2_hsum(a3));
        acc += __shfl_xor_sync(0xffffffffu, acc, 4);
        acc += __shfl_xor_sync(0xffffffffu, acc, 2);
        acc += __shfl_xor_sync(0xffffffffu, acc, 1);
        if (j == 0) red_s[lr] = acc;

        // ---- bar B (asymmetric): producers arrive, consumer syncs ----
        if (wid == 0) {
            asm volatile("bar.sync 1, %0;" :: "r"(NTH) : "memory");
            // ---- gate math + tagged publish (lanes 0..15) ----
            float hnew = 0.f;
            if (l < HPC) {
                const float* gi = &ring[t & (PD - 1)][0];
                float r = mufu_sigmoid(gi[l]       + red_s[l]);
                float z = mufu_sigmoid(gi[HPC + l] + red_s[HPC + l]);
                float n = mufu_tanh(fmaf(r, red_s[2 * HPC + l] + bhhn_s[l],
                                         gi[2 * HPC + l]));
                hnew = n + z * (hprev - n);          // (1-z)*n + z*h
                hprev = hnew;
                unsigned long long pk =
                    (unsigned long long)__float_as_uint(hnew) |
                    ((unsigned long long)(unsigned)(t + 1) << 32);
                asm volatile("st.relaxed.gpu.global.u64 [%0], %1;"
                             :: "l"(&g_ht[par ^ 1][hbase + l]), "l"(pk) : "memory");
                out[(size_t)t * HDIM + hbase + l] = hnew;  // off the serial path
            }
        } else {
            asm volatile("bar.arrive 1, %0;" :: "r"(NTH) : "memory");
        }
    }
}

// ---------------- launch ----------------
extern "C" void kernel_launch(void* const* d_in, const int* in_sizes, int n_in,
                              void* d_out, int out_size) {
    const float* x   = (const float*)d_in[0];
    const float* Wih = (const float*)d_in[1];
    const float* Whh = (const float*)d_in[2];
    const float* bih = (const float*)d_in[3];
    const float* bhh = (const float*)d_in[4];
    float* out = (float*)d_out;

    dim3 ggrid(GDIM / BN, T_STEPS / BM);   // (12, 128)
    gemm_gi<<<ggrid, 256>>>(x, Wih, bih, bhh);
    gru_scan<<<NCTA, NTH>>>(Whh, bhh, out);
}

// round 17
// speedup vs baseline: 3.0253x; 2.0326x over previous
#include <cuda_runtime.h>
#include <cstdint>
#include <cstddef>

// ---------------- problem constants ----------------
#define T_STEPS 16384
#define HDIM    512
#define GDIM    1536          // 3*H
#define NCTA    32
#define HPC     16            // h elements per CTA
#define RPC     48            // W_hh rows per CTA (3 gates x HPC)
#define NTH     384           // 12 warps; 8 lanes per row
#define POLLW   11            // poller / h-stager / gi-prefetch warp
#define PD      8             // gi ring depth

#define BM 128
#define BN 128
#define BK 8
#define GEMM_BN 12            // GDIM / BN
#define GEMM_BM 128           // T_STEPS / BM
#define GEMM_BLOCKS (GEMM_BN * GEMM_BM)   // 1536

// ---------------- device scratch ----------------
__device__ float              g_gi[(size_t)T_STEPS * GDIM]; // gi + folded biases
__device__ unsigned long long g_ht[2][HDIM];                // {tag:hi32, h:lo32}
__device__ unsigned           g_cnt[GEMM_BM];               // per-row-block done count

// ---------------- init: reset scan/gemm state ----------------
__global__ void init_k() {
    int t = threadIdx.x;
    unsigned long long* p = &g_ht[0][0];
    for (int i = t; i < 2 * HDIM; i += 512) p[i] = 0ULL;
    if (t < GEMM_BM) g_cnt[t] = 0u;
}

// ---------------- helpers ----------------
__device__ __forceinline__ uint32_t smem_u32(const void* p) {
    uint32_t a;
    asm("{ .reg .u64 t; cvta.to.shared.u64 t, %1; cvt.u32.u64 %0, t; }"
        : "=r"(a) : "l"(p));
    return a;
}
__device__ __forceinline__ float f32x2_hsum(unsigned long long a) {
    float lo, hi;
    asm("mov.b64 {%0,%1}, %2;" : "=f"(lo), "=f"(hi) : "l"(a));
    return lo + hi;
}
__device__ __forceinline__ float mufu_tanh(float x) {
    float r;
    asm("tanh.approx.f32 %0, %1;" : "=f"(r) : "f"(x));
    return r;
}
__device__ __forceinline__ float mufu_sigmoid(float x) {
    return fmaf(mufu_tanh(0.5f * x), 0.5f, 0.5f);
}

// ---------------- fused kernel: 32 scan blocks + 1536 GEMM blocks ----------
__global__ void __launch_bounds__(NTH, 1) fused_gru(
    const float* __restrict__ x,   const float* __restrict__ Wih,
    const float* __restrict__ bih, const float* __restrict__ bhh,
    const float* __restrict__ Whh, float* __restrict__ out) {

    // shared memory (both roles; union not possible with static decls)
    __shared__ __align__(16) float As[BK][BM];
    __shared__ __align__(16) float Bs[BK][BN];
    __shared__ __align__(16) float h_s[HDIM];
    __shared__ __align__(16) float ring[PD][RPC];
    __shared__ float red_s[RPC];
    __shared__ float bhhn_s[HPC];

    const int tid = threadIdx.x;

    // ==================== GEMM role ====================
    if (blockIdx.x >= NCTA) {
        const int g  = blockIdx.x - NCTA;
        const int bn = g % GEMM_BN;
        const int bm = g / GEMM_BN;
        const bool act = tid < 256;
        const int tx  = tid & 15;
        const int ty  = (tid >> 4) & 15;
        const int lrow = (tid >> 1) & 127;
        const int lseg = (tid & 1) * 4;
        const float* xp = x   + (size_t)(bm * BM + lrow) * HDIM + lseg;
        const float* wp = Wih + (size_t)(bn * BN + lrow) * HDIM + lseg;

        float acc[8][8];
#pragma unroll
        for (int i = 0; i < 8; i++)
#pragma unroll
            for (int j = 0; j < 8; j++) acc[i][j] = 0.f;

        for (int k0 = 0; k0 < HDIM; k0 += BK) {
            if (act) {
                float4 av = *(const float4*)(xp + k0);
                float4 bv = *(const float4*)(wp + k0);
                As[lseg + 0][lrow] = av.x; As[lseg + 1][lrow] = av.y;
                As[lseg + 2][lrow] = av.z; As[lseg + 3][lrow] = av.w;
                Bs[lseg + 0][lrow] = bv.x; Bs[lseg + 1][lrow] = bv.y;
                Bs[lseg + 2][lrow] = bv.z; Bs[lseg + 3][lrow] = bv.w;
            }
            __syncthreads();
            if (act) {
#pragma unroll
                for (int k = 0; k < BK; k++) {
                    float4 a0 = *(const float4*)&As[k][ty * 8];
                    float4 a1 = *(const float4*)&As[k][ty * 8 + 4];
                    float4 b0 = *(const float4*)&Bs[k][tx * 8];
                    float4 b1 = *(const float4*)&Bs[k][tx * 8 + 4];
                    float a[8] = {a0.x, a0.y, a0.z, a0.w, a1.x, a1.y, a1.z, a1.w};
                    float b[8] = {b0.x, b0.y, b0.z, b0.w, b1.x, b1.y, b1.z, b1.w};
#pragma unroll
                    for (int i = 0; i < 8; i++)
#pragma unroll
                        for (int j = 0; j < 8; j++)
                            acc[i][j] = fmaf(a[i], b[j], acc[i][j]);
                }
            }
            __syncthreads();
        }
        if (act) {
#pragma unroll
            for (int i = 0; i < 8; i++) {
                int row = bm * BM + ty * 8 + i;
                float* gp = &g_gi[(size_t)row * GDIM + bn * BN + tx * 8];
#pragma unroll
                for (int j = 0; j < 8; j++) {
                    int col = bn * BN + tx * 8 + j;
                    float b = bih[col];
                    if (col < 2 * HDIM) b += bhh[col];  // fold bhh for r,z gates
                    gp[j] = acc[i][j] + b;
                }
            }
        }
        __threadfence();                 // make gi stores gpu-visible
        __syncthreads();
        if (tid == 0)
            asm volatile("red.relaxed.gpu.global.add.u32 [%0], %1;"
                         :: "l"(&g_cnt[bm]), "r"(1u) : "memory");
        return;
    }

    // ==================== scan role (R10, gi gated on g_cnt) ====================
    const int c   = blockIdx.x;
    const int wid = tid >> 5;
    const int l   = tid & 31;
    const int lr  = tid >> 3;            // local row 0..47
    const int j   = tid & 7;             // lane within row

    // global row (gate-major: r,z,n blocks of HPC)
    const int gr = (lr / HPC) * HDIM + c * HPC + (lr % HPC);

    // ---- weights resident in registers: 16 x (u64,u64) ----
    unsigned long long wlo[16], whi[16];
    {
        const ulonglong2* wp =
            (const ulonglong2*)(Whh + (size_t)gr * HDIM + j * 4);
#pragma unroll
        for (int s = 0; s < 16; ++s) {
            ulonglong2 wv = __ldg(wp + s * 8);   // stride 128B
            wlo[s] = wv.x; whi[s] = wv.y;
        }
    }

    if (tid < HPC) bhhn_s[tid] = bhh[2 * HDIM + c * HPC + tid];

    // ---- gi ring prologue: rows 0..6 (all in row-block 0) once ready ----
    const uint32_t ring_u32 = smem_u32(&ring[0][0]);
    if (wid == POLLW) {
        unsigned rdy;
        do {
            asm volatile("ld.acquire.gpu.global.u32 %0, [%1];"
                         : "=r"(rdy) : "l"(&g_cnt[0]));
        } while (!__all_sync(0xffffffffu, rdy >= GEMM_BN));
#pragma unroll
        for (int p = 0; p < PD - 1; p++) {
            if (l < 12) {
                const float* src = &g_gi[(size_t)p * GDIM +
                                         (l >> 2) * HDIM + c * HPC + (l & 3) * 4];
                uint32_t dst = ring_u32 + (uint32_t)((p * RPC + l * 4) * 4);
                asm volatile("cp.async.cg.shared.global [%0], [%1], 16;"
                             :: "r"(dst), "l"(src));
            }
            asm volatile("cp.async.commit_group;");
        }
        asm volatile("cp.async.wait_group 0;");
    }

    const int hbase = c * HPC;
    float hprev = 0.f;
    __syncthreads();

    for (int t = 0; t < T_STEPS; ++t) {
        const int par = t & 1;
        int tp = t + PD - 1;
        if (tp >= T_STEPS) tp = T_STEPS - 1;

        // ---- poller warp: fused tagged capture (vote includes gi-row ready) ----
        if (wid == POLLW) {
            const unsigned long long* hb = &g_ht[par][0];
            const unsigned long long thr = (unsigned long long)(unsigned)t << 32;
            const unsigned* cp = &g_cnt[tp >> 7];
            unsigned long long q[16];
            for (;;) {
#pragma unroll
                for (int i = 0; i < 16; i++)
                    asm volatile("ld.relaxed.gpu.global.u64 %0, [%1];"
                                 : "=l"(q[i]) : "l"(hb + l + 32 * i));
                unsigned rdy;
                asm volatile("ld.acquire.gpu.global.u32 %0, [%1];"
                             : "=r"(rdy) : "l"(cp));
                bool ok = (rdy >= GEMM_BN);
#pragma unroll
                for (int i = 0; i < 16; i++) ok &= (q[i] >= thr);
                if (__all_sync(0xffffffffu, ok)) break;
            }
            // gi(tp) into ring slot tp&7 (safe: poll passed => slot consumed)
            if (l < 12) {
                const float* src = &g_gi[(size_t)tp * GDIM +
                                         (l >> 2) * HDIM + c * HPC + (l & 3) * 4];
                uint32_t dst = ring_u32 +
                    (uint32_t)(((tp & (PD - 1)) * RPC + l * 4) * 4);
                asm volatile("cp.async.cg.shared.global [%0], [%1], 16;"
                             :: "r"(dst), "l"(src));
            }
            asm volatile("cp.async.commit_group;");
            asm volatile("cp.async.wait_group 6;");
            // stage h(t): strip tags
#pragma unroll
            for (int i = 0; i < 16; i++)
                h_s[l + 32 * i] = __uint_as_float((unsigned)q[i]);
        }
        __syncthreads();                 // bar A: h_s + ring slot t ready

        // ---- matvec: weights from regs, h from SMEM (broadcast LDS.128) ----
        const float* hv = h_s + j * 4;
        unsigned long long a0 = 0ull, a1 = 0ull, a2 = 0ull, a3 = 0ull;
#pragma unroll
        for (int s = 0; s < 16; s += 2) {
            ulonglong2 p0 = *(const ulonglong2*)(hv + s * 32);
            ulonglong2 p1 = *(const ulonglong2*)(hv + (s + 1) * 32);
            asm("fma.rn.f32x2 %0, %1, %2, %0;" : "+l"(a0) : "l"(wlo[s]),     "l"(p0.x));
            asm("fma.rn.f32x2 %0, %1, %2, %0;" : "+l"(a1) : "l"(whi[s]),     "l"(p0.y));
            asm("fma.rn.f32x2 %0, %1, %2, %0;" : "+l"(a2) : "l"(wlo[s + 1]), "l"(p1.x));
            asm("fma.rn.f32x2 %0, %1, %2, %0;" : "+l"(a3) : "l"(whi[s + 1]), "l"(p1.y));
        }
        float acc = (f32x2_hsum(a0) + f32x2_hsum(a1)) +
                    (f32x2_hsum(a2) + f32x2_hsum(a3));
        acc += __shfl_xor_sync(0xffffffffu, acc, 4);
        acc += __shfl_xor_sync(0xffffffffu, acc, 2);
        acc += __shfl_xor_sync(0xffffffffu, acc, 1);
        if (j == 0) red_s[lr] = acc;
        __syncthreads();                 // bar B: red_s ready

        // ---- gate math + tagged publish (warp 0, lanes 0..15) ----
        if (wid == 0) {
            float hnew = 0.f;
            if (l < HPC) {
                const float* gi = &ring[t & (PD - 1)][0];
                float r = mufu_sigmoid(gi[l]       + red_s[l]);
                float z = mufu_sigmoid(gi[HPC + l] + red_s[HPC + l]);
                float n = mufu_tanh(fmaf(r, red_s[2 * HPC + l] + bhhn_s[l],
                                         gi[2 * HPC + l]));
                hnew = n + z * (hprev - n);          // (1-z)*n + z*h
                hprev = hnew;
                unsigned long long pk =
                    (unsigned long long)__float_as_uint(hnew) |
                    ((unsigned long long)(unsigned)(t + 1) << 32);
                asm volatile("st.relaxed.gpu.global.u64 [%0], %1;"
                             :: "l"(&g_ht[par ^ 1][hbase + l]), "l"(pk) : "memory");
                out[(size_t)t * HDIM + hbase + l] = hnew;  // off the serial path
            }
        }
    }
}

// ---------------- launch ----------------
extern "C" void kernel_launch(void* const* d_in, const int* in_sizes, int n_in,
                              void* d_out, int out_size) {
    const float* x   = (const float*)d_in[0];
    const float* Wih = (const float*)d_in[1];
    const float* Whh = (const float*)d_in[2];
    const float* bih = (const float*)d_in[3];
    const float* bhh = (const float*)d_in[4];
    float* out = (float*)d_out;

    init_k<<<1, 512>>>();
    fused_gru<<<NCTA + GEMM_BLOCKS, NTH>>>(x, Wih, bih, bhh, Whh, out);
}